// round 1
// baseline (speedup 1.0000x reference)
#include <cuda_runtime.h>

#define N_NET 4096
#define NPTS  512        // points per network
#define PC    63         // position channels
#define DC    27         // direction channels
#define CIN   (PC + DC)  // 90
#define H     32
#define DHID  32
#define TPB   128        // threads per CTA = points per chunk
#define NCHUNK (NPTS / TPB)
#define XS    91         // padded x stride in smem (gcd(91,32)=1 -> conflict-free)

struct __align__(16) SmemLayout {
    float W0[H * PC];         // 2016
    float b0[H];
    float W1[H * H];          // 1024
    float b1[H];
    float Wa[H];              // [1, H]
    float ba[4];
    float Wf[H * H];          // 1024
    float bf[H];
    float Wd[DHID * (H + DC)];// 32*59 = 1888
    float bd[DHID];
    float Wr[3 * DHID];       // 96
    float br[4];
    float x[TPB * XS];        // 11648
};

__device__ __forceinline__ void coop_copy(float* dst, const float* src, int n, int t) {
    for (int i = t; i < n; i += TPB) dst[i] = src[i];
}

__global__ __launch_bounds__(TPB) void kilonerf_kernel(
    const float* __restrict__ gx,
    const float* __restrict__ gW0, const float* __restrict__ gb0,
    const float* __restrict__ gW1, const float* __restrict__ gb1,
    const float* __restrict__ gWa, const float* __restrict__ gba,
    const float* __restrict__ gWf, const float* __restrict__ gbf,
    const float* __restrict__ gWd, const float* __restrict__ gbd,
    const float* __restrict__ gWr, const float* __restrict__ gbr,
    float* __restrict__ gout)
{
    extern __shared__ char smem_raw[];
    SmemLayout& sm = *reinterpret_cast<SmemLayout*>(smem_raw);

    const int n = blockIdx.x;
    const int t = threadIdx.x;

    // ---- stage this network's weights into smem (coalesced, once) ----
    coop_copy(sm.W0, gW0 + (size_t)n * H * PC,          H * PC,          t);
    coop_copy(sm.b0, gb0 + (size_t)n * H,               H,               t);
    coop_copy(sm.W1, gW1 + (size_t)n * H * H,           H * H,           t);
    coop_copy(sm.b1, gb1 + (size_t)n * H,               H,               t);
    coop_copy(sm.Wa, gWa + (size_t)n * H,               H,               t);
    coop_copy(sm.Wf, gWf + (size_t)n * H * H,           H * H,           t);
    coop_copy(sm.bf, gbf + (size_t)n * H,               H,               t);
    coop_copy(sm.Wd, gWd + (size_t)n * DHID * (H + DC), DHID * (H + DC), t);
    coop_copy(sm.bd, gbd + (size_t)n * DHID,            DHID,            t);
    coop_copy(sm.Wr, gWr + (size_t)n * 3 * DHID,        3 * DHID,        t);
    if (t == 0) {
        sm.ba[0] = gba[n];
        sm.br[0] = gbr[(size_t)n * 3 + 0];
        sm.br[1] = gbr[(size_t)n * 3 + 1];
        sm.br[2] = gbr[(size_t)n * 3 + 2];
    }

    for (int chunk = 0; chunk < NCHUNK; chunk++) {
        // ---- stage x chunk (coalesced global reads, padded smem rows) ----
        const float* gxc = gx + ((size_t)n * NPTS + (size_t)chunk * TPB) * CIN;
        for (int idx = t; idx < TPB * CIN; idx += TPB) {
            int r = idx / CIN;
            int c = idx - r * CIN;
            sm.x[r * XS + c] = gxc[idx];
        }
        __syncthreads();   // weights (first iter) + x chunk ready

        const float* __restrict__ xp = &sm.x[t * XS];

        // ---- layer 0: h = relu(W0 @ pos + b0), W0 [H, PC] ----
        float h[H];
        #pragma unroll
        for (int og = 0; og < H; og += 4) {
            float a0 = sm.b0[og + 0];
            float a1 = sm.b0[og + 1];
            float a2 = sm.b0[og + 2];
            float a3 = sm.b0[og + 3];
            const float* w0 = &sm.W0[(og + 0) * PC];
            const float* w1 = &sm.W0[(og + 1) * PC];
            const float* w2 = &sm.W0[(og + 2) * PC];
            const float* w3 = &sm.W0[(og + 3) * PC];
            #pragma unroll
            for (int i = 0; i < PC; i++) {
                float xi = xp[i];
                a0 = fmaf(w0[i], xi, a0);
                a1 = fmaf(w1[i], xi, a1);
                a2 = fmaf(w2[i], xi, a2);
                a3 = fmaf(w3[i], xi, a3);
            }
            h[og + 0] = fmaxf(a0, 0.f);
            h[og + 1] = fmaxf(a1, 0.f);
            h[og + 2] = fmaxf(a2, 0.f);
            h[og + 3] = fmaxf(a3, 0.f);
        }

        // ---- layer 1: h2 = relu(W1 @ h + b1) ----
        float h2[H];
        #pragma unroll
        for (int og = 0; og < H; og += 4) {
            float a0 = sm.b1[og + 0];
            float a1 = sm.b1[og + 1];
            float a2 = sm.b1[og + 2];
            float a3 = sm.b1[og + 3];
            #pragma unroll
            for (int i = 0; i < H; i++) {
                float hi = h[i];
                a0 = fmaf(sm.W1[(og + 0) * H + i], hi, a0);
                a1 = fmaf(sm.W1[(og + 1) * H + i], hi, a1);
                a2 = fmaf(sm.W1[(og + 2) * H + i], hi, a2);
                a3 = fmaf(sm.W1[(og + 3) * H + i], hi, a3);
            }
            h2[og + 0] = fmaxf(a0, 0.f);
            h2[og + 1] = fmaxf(a1, 0.f);
            h2[og + 2] = fmaxf(a2, 0.f);
            h2[og + 3] = fmaxf(a3, 0.f);
        }

        // ---- alpha = Wa @ h2 + ba  (no relu) ----
        float aa = sm.ba[0], ab = 0.f;
        #pragma unroll
        for (int i = 0; i < H; i += 2) {
            aa = fmaf(sm.Wa[i + 0], h2[i + 0], aa);
            ab = fmaf(sm.Wa[i + 1], h2[i + 1], ab);
        }
        float alpha = aa + ab;

        // ---- feature = Wf @ h2 + bf  (no relu) ----
        float f[H];
        #pragma unroll
        for (int og = 0; og < H; og += 4) {
            float a0 = sm.bf[og + 0];
            float a1 = sm.bf[og + 1];
            float a2 = sm.bf[og + 2];
            float a3 = sm.bf[og + 3];
            #pragma unroll
            for (int i = 0; i < H; i++) {
                float hi = h2[i];
                a0 = fmaf(sm.Wf[(og + 0) * H + i], hi, a0);
                a1 = fmaf(sm.Wf[(og + 1) * H + i], hi, a1);
                a2 = fmaf(sm.Wf[(og + 2) * H + i], hi, a2);
                a3 = fmaf(sm.Wf[(og + 3) * H + i], hi, a3);
            }
            f[og + 0] = a0;
            f[og + 1] = a1;
            f[og + 2] = a2;
            f[og + 3] = a3;
        }

        // ---- direction layer: hd = relu(Wd @ [feature, dir] + bd), Wd [D, H+DC] ----
        const int WDC = H + DC;  // 59
        float hd[DHID];
        #pragma unroll
        for (int og = 0; og < DHID; og += 4) {
            float a0 = sm.bd[og + 0];
            float a1 = sm.bd[og + 1];
            float a2 = sm.bd[og + 2];
            float a3 = sm.bd[og + 3];
            #pragma unroll
            for (int i = 0; i < H; i++) {
                float fi = f[i];
                a0 = fmaf(sm.Wd[(og + 0) * WDC + i], fi, a0);
                a1 = fmaf(sm.Wd[(og + 1) * WDC + i], fi, a1);
                a2 = fmaf(sm.Wd[(og + 2) * WDC + i], fi, a2);
                a3 = fmaf(sm.Wd[(og + 3) * WDC + i], fi, a3);
            }
            #pragma unroll
            for (int j = 0; j < DC; j++) {
                float dj = xp[PC + j];
                a0 = fmaf(sm.Wd[(og + 0) * WDC + H + j], dj, a0);
                a1 = fmaf(sm.Wd[(og + 1) * WDC + H + j], dj, a1);
                a2 = fmaf(sm.Wd[(og + 2) * WDC + H + j], dj, a2);
                a3 = fmaf(sm.Wd[(og + 3) * WDC + H + j], dj, a3);
            }
            hd[og + 0] = fmaxf(a0, 0.f);
            hd[og + 1] = fmaxf(a1, 0.f);
            hd[og + 2] = fmaxf(a2, 0.f);
            hd[og + 3] = fmaxf(a3, 0.f);
        }

        // ---- rgb = Wr @ hd + br ----
        float r0 = sm.br[0], r1 = sm.br[1], r2 = sm.br[2];
        #pragma unroll
        for (int i = 0; i < DHID; i++) {
            float hi = hd[i];
            r0 = fmaf(sm.Wr[0 * DHID + i], hi, r0);
            r1 = fmaf(sm.Wr[1 * DHID + i], hi, r1);
            r2 = fmaf(sm.Wr[2 * DHID + i], hi, r2);
        }

        // ---- write [rgb, alpha] as one float4 ----
        float4 o4 = make_float4(r0, r1, r2, alpha);
        reinterpret_cast<float4*>(gout)[(size_t)n * NPTS + (size_t)chunk * TPB + t] = o4;

        __syncthreads();   // protect sm.x before next chunk's load
    }
}

extern "C" void kernel_launch(void* const* d_in, const int* in_sizes, int n_in,
                              void* d_out, int out_size)
{
    const float* gx  = (const float*)d_in[0];
    const float* gW0 = (const float*)d_in[1];
    const float* gb0 = (const float*)d_in[2];
    const float* gW1 = (const float*)d_in[3];
    const float* gb1 = (const float*)d_in[4];
    const float* gWa = (const float*)d_in[5];
    const float* gba = (const float*)d_in[6];
    const float* gWf = (const float*)d_in[7];
    const float* gbf = (const float*)d_in[8];
    const float* gWd = (const float*)d_in[9];
    const float* gbd = (const float*)d_in[10];
    const float* gWr = (const float*)d_in[11];
    const float* gbr = (const float*)d_in[12];
    float* gout = (float*)d_out;

    const int smem_bytes = (int)sizeof(SmemLayout);
    cudaFuncSetAttribute(kilonerf_kernel,
                         cudaFuncAttributeMaxDynamicSharedMemorySize, smem_bytes);

    kilonerf_kernel<<<N_NET, TPB, smem_bytes>>>(
        gx, gW0, gb0, gW1, gb1, gWa, gba, gWf, gbf, gWd, gbd, gWr, gbr, gout);
}

// round 2
// speedup vs baseline: 1.7701x; 1.7701x over previous
#include <cuda_runtime.h>
#include <cstdint>

#define N_NET 4096
#define NPTS  512
#define PC    63
#define DC    27
#define CIN   90
#define H     32
#define TPB   128

// smem strides chosen so stride % 32 == 4  ->  bank(row*S + k) = 4*row + k  (bijective over warp)
#define S68 68   // K-dim 64-ish tiles (W0, Wd, posS, dA)
#define S36 36   // K-dim 32 tiles (W1, Wfa, Wr, hS)

struct __align__(16) Smem {
    // weights (tf32 bit patterns stored as uint)
    uint32_t W0[32 * S68];    // [out=32][k<63, pad], k=63 zero
    uint32_t W1[32 * S36];    // [32][k<32]
    uint32_t Wfa[40 * S36];   // rows 0-31 = Wf, row 32 = Wa, rows 33-39 zero
    uint32_t Wd[32 * S68];    // [32][k<59], 59-63 zero
    uint32_t Wr[8 * S36];     // rows 0-2 = Wr, 3-7 zero
    float b0[32], b1[32], bfa[40], bd[32], br[4];
    // per-warp scratch
    uint32_t posS[4][16 * S68];  // positions (k<63), col 63 zero
    uint32_t dA[4][16 * S68];    // dir-layer A: cols 0-31 feat, 32-58 dirs, 59-63 zero
    uint32_t hS[4][16 * S36];    // inter-layer activations (h1/h2/hd)
    float alphaS[4][16];
};

__device__ __forceinline__ uint32_t f2tf(float x) {
    uint32_t u;
    asm("cvt.rna.tf32.f32 %0, %1;" : "=r"(u) : "f"(x));
    return u;
}

__device__ __forceinline__ void mma_tf32(float& c0, float& c1, float& c2, float& c3,
                                         uint32_t a0, uint32_t a1, uint32_t a2, uint32_t a3,
                                         uint32_t b0, uint32_t b1) {
    asm("mma.sync.aligned.m16n8k8.row.col.f32.tf32.tf32.f32 "
        "{%0,%1,%2,%3}, {%4,%5,%6,%7}, {%8,%9}, {%0,%1,%2,%3};"
        : "+f"(c0), "+f"(c1), "+f"(c2), "+f"(c3)
        : "r"(a0), "r"(a1), "r"(a2), "r"(a3), "r"(b0), "r"(b1));
}

__global__ __launch_bounds__(TPB, 3) void kilonerf_mma_kernel(
    const float* __restrict__ gx,
    const float* __restrict__ gW0, const float* __restrict__ gb0,
    const float* __restrict__ gW1, const float* __restrict__ gb1,
    const float* __restrict__ gWa, const float* __restrict__ gba,
    const float* __restrict__ gWf, const float* __restrict__ gbf,
    const float* __restrict__ gWd, const float* __restrict__ gbd,
    const float* __restrict__ gWr, const float* __restrict__ gbr,
    float* __restrict__ gout)
{
    extern __shared__ char smem_raw[];
    Smem& sm = *reinterpret_cast<Smem*>(smem_raw);

    const int n = blockIdx.x;
    const int t = threadIdx.x;
    const int w = t >> 5;        // warp id 0..3
    const int l = t & 31;        // lane
    const int g = l >> 2;        // groupID (row base)
    const int q = l & 3;         // threadID_in_group

    // ---------------- stage weights (zero-fill then copy+cvt) ----------------
    {
        // zero entire weight + bias region (contiguous at struct start)
        const int zwords = (32 * S68 + 32 * S36 + 40 * S36 + 32 * S68 + 8 * S36) + (32 + 32 + 40 + 32 + 4);
        uint32_t* zp = sm.W0;
        for (int i = t; i < zwords; i += TPB) zp[i] = 0u;
        __syncthreads();

        const float* p;
        p = gW0 + (size_t)n * 32 * 63;
        for (int i = t; i < 32 * 63; i += TPB) { int r = i / 63, c = i - r * 63; sm.W0[r * S68 + c] = f2tf(p[i]); }
        p = gW1 + (size_t)n * 32 * 32;
        for (int i = t; i < 32 * 32; i += TPB) { int r = i >> 5, c = i & 31; sm.W1[r * S36 + c] = f2tf(p[i]); }
        p = gWf + (size_t)n * 32 * 32;
        for (int i = t; i < 32 * 32; i += TPB) { int r = i >> 5, c = i & 31; sm.Wfa[r * S36 + c] = f2tf(p[i]); }
        p = gWa + (size_t)n * 32;
        if (t < 32) sm.Wfa[32 * S36 + t] = f2tf(p[t]);
        p = gWd + (size_t)n * 32 * 59;
        for (int i = t; i < 32 * 59; i += TPB) { int r = i / 59, c = i - r * 59; sm.Wd[r * S68 + c] = f2tf(p[i]); }
        p = gWr + (size_t)n * 3 * 32;
        if (t < 96) { int r = t >> 5, c = t & 31; sm.Wr[r * S36 + c] = f2tf(p[t]); }
        // biases (plain f32)
        if (t < 32) sm.b0[t] = gb0[(size_t)n * 32 + t];
        else if (t < 64) sm.b1[t - 32] = gb1[(size_t)n * 32 + (t - 32)];
        else if (t < 96) sm.bfa[t - 64] = gbf[(size_t)n * 32 + (t - 64)];
        else sm.bd[t - 96] = gbd[(size_t)n * 32 + (t - 96)];
        if (t == 0) {
            sm.bfa[32] = gba[n];
            sm.br[0] = gbr[(size_t)n * 3 + 0];
            sm.br[1] = gbr[(size_t)n * 3 + 1];
            sm.br[2] = gbr[(size_t)n * 3 + 2];
        }
        // per-warp scratch zero pads: posS col 63; dA cols 59-63
        if (l < 16) sm.posS[w][l * S68 + 63] = 0u;
        for (int i = l; i < 16 * 5; i += 32) { int r = i / 5, c = i - r * 5; sm.dA[w][r * S68 + 59 + c] = 0u; }
    }
    __syncthreads();

    uint32_t* const posS = sm.posS[w];
    uint32_t* const dAp  = sm.dA[w];
    uint32_t* const hSp  = sm.hS[w];
    float*    const alS  = sm.alphaS[w];

    // ---------------- preload L0 B-fragments (reused across all 8 M-tiles) ----------------
    uint32_t B0[8][4][2];
    #pragma unroll
    for (int ks = 0; ks < 8; ks++) {
        const int k0 = q + 8 * ks;
        #pragma unroll
        for (int nt = 0; nt < 4; nt++) {
            B0[ks][nt][0] = sm.W0[(nt * 8 + g) * S68 + k0];
            B0[ks][nt][1] = sm.W0[(nt * 8 + g) * S68 + k0 + 4];
        }
    }

    // ---------------- per-tile pipeline ----------------
    for (int tile = 0; tile < 8; tile++) {
        const long ptg = (long)n * NPTS + w * 128 + tile * 16;   // global point index base

        // stage x tile: positions -> posS (cols 0..62), dirs -> dA cols 32..58 (all cvt to tf32)
        const float* gxt = gx + (size_t)ptg * CIN;
        for (int i = l; i < 16 * CIN; i += 32) {
            int r = i / CIN, c = i - r * CIN;
            uint32_t u = f2tf(gxt[i]);
            if (c < PC) posS[r * S68 + c] = u;
            else        dAp[r * S68 + 32 + (c - PC)] = u;
        }
        __syncwarp();

        // ---- L0: h1 = relu(W0 @ pos + b0), K=64 (col63 zero) ----
        float acc[4][4];
        #pragma unroll
        for (int nt = 0; nt < 4; nt++) { acc[nt][0] = acc[nt][1] = acc[nt][2] = acc[nt][3] = 0.f; }
        #pragma unroll
        for (int ks = 0; ks < 8; ks++) {
            const int k0 = q + 8 * ks;
            uint32_t a0 = posS[g * S68 + k0];
            uint32_t a1 = posS[(g + 8) * S68 + k0];
            uint32_t a2 = posS[g * S68 + k0 + 4];
            uint32_t a3 = posS[(g + 8) * S68 + k0 + 4];
            #pragma unroll
            for (int nt = 0; nt < 4; nt++)
                mma_tf32(acc[nt][0], acc[nt][1], acc[nt][2], acc[nt][3],
                         a0, a1, a2, a3, B0[ks][nt][0], B0[ks][nt][1]);
        }
        #pragma unroll
        for (int nt = 0; nt < 4; nt++) {
            const int col = nt * 8 + 2 * q;
            float bc0 = sm.b0[col], bc1 = sm.b0[col + 1];
            uint32_t u0 = f2tf(fmaxf(acc[nt][0] + bc0, 0.f));
            uint32_t u1 = f2tf(fmaxf(acc[nt][1] + bc1, 0.f));
            uint32_t u2 = f2tf(fmaxf(acc[nt][2] + bc0, 0.f));
            uint32_t u3 = f2tf(fmaxf(acc[nt][3] + bc1, 0.f));
            *reinterpret_cast<uint2*>(&hSp[g * S36 + col])       = make_uint2(u0, u1);
            *reinterpret_cast<uint2*>(&hSp[(g + 8) * S36 + col]) = make_uint2(u2, u3);
        }
        __syncwarp();

        // ---- L1: h2 = relu(W1 @ h1 + b1), K=32 ----
        #pragma unroll
        for (int nt = 0; nt < 4; nt++) { acc[nt][0] = acc[nt][1] = acc[nt][2] = acc[nt][3] = 0.f; }
        #pragma unroll
        for (int ks = 0; ks < 4; ks++) {
            const int k0 = q + 8 * ks;
            uint32_t a0 = hSp[g * S36 + k0];
            uint32_t a1 = hSp[(g + 8) * S36 + k0];
            uint32_t a2 = hSp[g * S36 + k0 + 4];
            uint32_t a3 = hSp[(g + 8) * S36 + k0 + 4];
            #pragma unroll
            for (int nt = 0; nt < 4; nt++) {
                uint32_t b0f = sm.W1[(nt * 8 + g) * S36 + k0];
                uint32_t b1f = sm.W1[(nt * 8 + g) * S36 + k0 + 4];
                mma_tf32(acc[nt][0], acc[nt][1], acc[nt][2], acc[nt][3], a0, a1, a2, a3, b0f, b1f);
            }
        }
        __syncwarp();   // all h1 reads done before overwrite
        #pragma unroll
        for (int nt = 0; nt < 4; nt++) {
            const int col = nt * 8 + 2 * q;
            float bc0 = sm.b1[col], bc1 = sm.b1[col + 1];
            uint32_t u0 = f2tf(fmaxf(acc[nt][0] + bc0, 0.f));
            uint32_t u1 = f2tf(fmaxf(acc[nt][1] + bc1, 0.f));
            uint32_t u2 = f2tf(fmaxf(acc[nt][2] + bc0, 0.f));
            uint32_t u3 = f2tf(fmaxf(acc[nt][3] + bc1, 0.f));
            *reinterpret_cast<uint2*>(&hSp[g * S36 + col])       = make_uint2(u0, u1);
            *reinterpret_cast<uint2*>(&hSp[(g + 8) * S36 + col]) = make_uint2(u2, u3);
        }
        __syncwarp();

        // ---- L2: [feature | alpha] = Wfa @ h2 + bfa (no relu), 5 N-tiles ----
        float acc5[5][4];
        #pragma unroll
        for (int nt = 0; nt < 5; nt++) { acc5[nt][0] = acc5[nt][1] = acc5[nt][2] = acc5[nt][3] = 0.f; }
        #pragma unroll
        for (int ks = 0; ks < 4; ks++) {
            const int k0 = q + 8 * ks;
            uint32_t a0 = hSp[g * S36 + k0];
            uint32_t a1 = hSp[(g + 8) * S36 + k0];
            uint32_t a2 = hSp[g * S36 + k0 + 4];
            uint32_t a3 = hSp[(g + 8) * S36 + k0 + 4];
            #pragma unroll
            for (int nt = 0; nt < 5; nt++) {
                uint32_t b0f = sm.Wfa[(nt * 8 + g) * S36 + k0];
                uint32_t b1f = sm.Wfa[(nt * 8 + g) * S36 + k0 + 4];
                mma_tf32(acc5[nt][0], acc5[nt][1], acc5[nt][2], acc5[nt][3], a0, a1, a2, a3, b0f, b1f);
            }
        }
        __syncwarp();
        #pragma unroll
        for (int nt = 0; nt < 4; nt++) {           // feature -> dA cols 0..31 (tf32)
            const int col = nt * 8 + 2 * q;
            float bc0 = sm.bfa[col], bc1 = sm.bfa[col + 1];
            uint32_t u0 = f2tf(acc5[nt][0] + bc0);
            uint32_t u1 = f2tf(acc5[nt][1] + bc1);
            uint32_t u2 = f2tf(acc5[nt][2] + bc0);
            uint32_t u3 = f2tf(acc5[nt][3] + bc1);
            *reinterpret_cast<uint2*>(&dAp[g * S68 + col])       = make_uint2(u0, u1);
            *reinterpret_cast<uint2*>(&dAp[(g + 8) * S68 + col]) = make_uint2(u2, u3);
        }
        if (q == 0) {                              // alpha = col 32
            float ba = sm.bfa[32];
            alS[g]     = acc5[4][0] + ba;
            alS[g + 8] = acc5[4][2] + ba;
        }
        __syncwarp();

        // ---- L3: hd = relu(Wd @ [feat|dirs] + bd), K=64 (59-63 zero) ----
        #pragma unroll
        for (int nt = 0; nt < 4; nt++) { acc[nt][0] = acc[nt][1] = acc[nt][2] = acc[nt][3] = 0.f; }
        #pragma unroll
        for (int ks = 0; ks < 8; ks++) {
            const int k0 = q + 8 * ks;
            uint32_t a0 = dAp[g * S68 + k0];
            uint32_t a1 = dAp[(g + 8) * S68 + k0];
            uint32_t a2 = dAp[g * S68 + k0 + 4];
            uint32_t a3 = dAp[(g + 8) * S68 + k0 + 4];
            #pragma unroll
            for (int nt = 0; nt < 4; nt++) {
                uint32_t b0f = sm.Wd[(nt * 8 + g) * S68 + k0];
                uint32_t b1f = sm.Wd[(nt * 8 + g) * S68 + k0 + 4];
                mma_tf32(acc[nt][0], acc[nt][1], acc[nt][2], acc[nt][3], a0, a1, a2, a3, b0f, b1f);
            }
        }
        __syncwarp();
        #pragma unroll
        for (int nt = 0; nt < 4; nt++) {
            const int col = nt * 8 + 2 * q;
            float bc0 = sm.bd[col], bc1 = sm.bd[col + 1];
            uint32_t u0 = f2tf(fmaxf(acc[nt][0] + bc0, 0.f));
            uint32_t u1 = f2tf(fmaxf(acc[nt][1] + bc1, 0.f));
            uint32_t u2 = f2tf(fmaxf(acc[nt][2] + bc0, 0.f));
            uint32_t u3 = f2tf(fmaxf(acc[nt][3] + bc1, 0.f));
            *reinterpret_cast<uint2*>(&hSp[g * S36 + col])       = make_uint2(u0, u1);
            *reinterpret_cast<uint2*>(&hSp[(g + 8) * S36 + col]) = make_uint2(u2, u3);
        }
        __syncwarp();

        // ---- L4: rgb = Wr @ hd + br (N-tile 0 only; rows 3-7 of Wr are zero) ----
        float r0 = 0.f, r1 = 0.f, r2 = 0.f, r3 = 0.f;
        #pragma unroll
        for (int ks = 0; ks < 4; ks++) {
            const int k0 = q + 8 * ks;
            uint32_t a0 = hSp[g * S36 + k0];
            uint32_t a1 = hSp[(g + 8) * S36 + k0];
            uint32_t a2 = hSp[g * S36 + k0 + 4];
            uint32_t a3 = hSp[(g + 8) * S36 + k0 + 4];
            uint32_t b0f = sm.Wr[g * S36 + k0];
            uint32_t b1f = sm.Wr[g * S36 + k0 + 4];
            mma_tf32(r0, r1, r2, r3, a0, a1, a2, a3, b0f, b1f);
        }

        // ---- write out [rgb, alpha] ----
        float2* out2 = reinterpret_cast<float2*>(gout);
        if (q == 0) {          // cols 0,1 -> .x, .y
            out2[(ptg + g) * 2]     = make_float2(r0 + sm.br[0], r1 + sm.br[1]);
            out2[(ptg + g + 8) * 2] = make_float2(r2 + sm.br[0], r3 + sm.br[1]);
        } else if (q == 1) {   // col 2 -> .z, alpha -> .w
            out2[(ptg + g) * 2 + 1]     = make_float2(r0 + sm.br[2], alS[g]);
            out2[(ptg + g + 8) * 2 + 1] = make_float2(r2 + sm.br[2], alS[g + 8]);
        }
        __syncwarp();   // protect scratch before next tile
    }
}

extern "C" void kernel_launch(void* const* d_in, const int* in_sizes, int n_in,
                              void* d_out, int out_size)
{
    const float* gx  = (const float*)d_in[0];
    const float* gW0 = (const float*)d_in[1];
    const float* gb0 = (const float*)d_in[2];
    const float* gW1 = (const float*)d_in[3];
    const float* gb1 = (const float*)d_in[4];
    const float* gWa = (const float*)d_in[5];
    const float* gba = (const float*)d_in[6];
    const float* gWf = (const float*)d_in[7];
    const float* gbf = (const float*)d_in[8];
    const float* gWd = (const float*)d_in[9];
    const float* gbd = (const float*)d_in[10];
    const float* gWr = (const float*)d_in[11];
    const float* gbr = (const float*)d_in[12];
    float* gout = (float*)d_out;

    const int smem_bytes = (int)sizeof(Smem);
    cudaFuncSetAttribute(kilonerf_mma_kernel,
                         cudaFuncAttributeMaxDynamicSharedMemorySize, smem_bytes);

    kilonerf_mma_kernel<<<N_NET, TPB, smem_bytes>>>(
        gx, gW0, gb0, gW1, gb1, gWa, gba, gWf, gbf, gWd, gbd, gWr, gbr, gout);
}

// round 3
// speedup vs baseline: 3.0154x; 1.7036x over previous
#include <cuda_runtime.h>
#include <cstdint>

#define N_NET 4096
#define NPTS  512
#define PC    63
#define DC    27
#define CIN   90
#define TPB   128

#define S68 68   // stride for K=64 weight tiles (mod 32 == 4)
#define S36 36   // stride for K=32 tiles / activations (mod 32 == 4)

struct __align__(16) Smem {
    uint32_t W0[32 * S68];    // [out=32][K=64 perm]; col 63 = b0 (bias-in-K)
    uint32_t W1[32 * S36];    // [32][32 perm]
    uint32_t Wfa[40 * S36];   // rows 0-31 Wf, row 32 Wa, 33-39 zero
    uint32_t Wd[32 * S68];    // [32][K=64 perm]; col 59 = bd, 60-63 zero
    uint32_t Wr[8 * S36];     // rows 0-2 Wr, 3-7 zero
    float b1[32];
    float bfa[34];            // [32] = ba
    float br[4];
    uint32_t hS[4][16 * S36]; // per-warp activation scratch (perm layout)
    float alphaS[4][16];
};

// number of 32-bit words to zero-fill (weights + biases)
#define ZWORDS (32*S68 + 32*S36 + 40*S36 + 32*S68 + 8*S36 + 32 + 34 + 4)

__device__ __forceinline__ uint32_t f2tf(float x) {
    uint32_t u;
    asm("cvt.rna.tf32.f32 %0, %1;" : "=r"(u) : "f"(x));
    return u;
}

// pair-permutation: within each 8-group store order (0,4,1,5,2,6,3,7)
// -> lane q reads (k=q, k=q+4) as one 64-bit word at offset 8*ks + 2*q
__device__ __forceinline__ int ppos(int k) {
    return (k & ~7) | (((k & 3) << 1) | ((k & 7) >> 2));
}

__device__ __forceinline__ void mma_tf32(float& c0, float& c1, float& c2, float& c3,
                                         uint32_t a0, uint32_t a1, uint32_t a2, uint32_t a3,
                                         uint32_t b0, uint32_t b1) {
    asm("mma.sync.aligned.m16n8k8.row.col.f32.tf32.tf32.f32 "
        "{%0,%1,%2,%3}, {%4,%5,%6,%7}, {%8,%9}, {%0,%1,%2,%3};"
        : "+f"(c0), "+f"(c1), "+f"(c2), "+f"(c3)
        : "r"(a0), "r"(a1), "r"(a2), "r"(a3), "r"(b0), "r"(b1));
}

#define ONE_TF 0x3F800000u

__global__ __launch_bounds__(TPB, 5) void kilonerf_mma_kernel(
    const float* __restrict__ gx,
    const float* __restrict__ gW0, const float* __restrict__ gb0,
    const float* __restrict__ gW1, const float* __restrict__ gb1,
    const float* __restrict__ gWa, const float* __restrict__ gba,
    const float* __restrict__ gWf, const float* __restrict__ gbf,
    const float* __restrict__ gWd, const float* __restrict__ gbd,
    const float* __restrict__ gWr, const float* __restrict__ gbr,
    float* __restrict__ gout)
{
    extern __shared__ char smem_raw[];
    Smem& sm = *reinterpret_cast<Smem*>(smem_raw);

    const int n = blockIdx.x;
    const int t = threadIdx.x;
    const int w = t >> 5;
    const int l = t & 31;
    const int g = l >> 2;        // groupID (row within 8)
    const int q = l & 3;         // threadID_in_group
    // epilogue permuted store offsets for cols 2q, 2q+1 within an 8-group
    const int off0 = (q < 2) ? 4 * q : 4 * q - 7;
    const int off1 = off0 + 2;

    // ---------------- zero weights+biases, then stage (permuted, tf32) ----------------
    {
        uint32_t* zp = sm.W0;
        for (int i = t; i < ZWORDS; i += TPB) zp[i] = 0u;
        __syncthreads();

        const float* p;
        p = gW0 + (size_t)n * 32 * 63;
        for (int i = t; i < 32 * 63; i += TPB) { int r = i / 63, k = i - r * 63; sm.W0[r * S68 + ppos(k)] = f2tf(p[i]); }
        p = gW1 + (size_t)n * 1024;
        for (int i = t; i < 1024; i += TPB) { int r = i >> 5, k = i & 31; sm.W1[r * S36 + ppos(k)] = f2tf(p[i]); }
        p = gWf + (size_t)n * 1024;
        for (int i = t; i < 1024; i += TPB) { int r = i >> 5, k = i & 31; sm.Wfa[r * S36 + ppos(k)] = f2tf(p[i]); }
        p = gWd + (size_t)n * 32 * 59;
        for (int i = t; i < 32 * 59; i += TPB) { int r = i / 59, k = i - r * 59; sm.Wd[r * S68 + ppos(k)] = f2tf(p[i]); }
        if (t < 32) {
            sm.Wfa[32 * S36 + ppos(t)] = f2tf(gWa[(size_t)n * 32 + t]);   // Wa row
            sm.W0[t * S68 + 63] = f2tf(gb0[(size_t)n * 32 + t]);          // b0 at k=63 (ppos(63)=63)
            sm.Wd[t * S68 + 62] = f2tf(gbd[(size_t)n * 32 + t]);          // bd at k=59 (ppos(59)=62)
            sm.b1[t]  = gb1[(size_t)n * 32 + t];
            sm.bfa[t] = gbf[(size_t)n * 32 + t];
        }
        if (t >= 32 && t < 128) { int i = t - 32; int r = i >> 5, k = i & 31; sm.Wr[r * S36 + ppos(k)] = f2tf(gWr[(size_t)n * 96 + i]); }
        if (t == 0) {
            sm.bfa[32] = gba[n];
            sm.br[0] = gbr[(size_t)n * 3 + 0];
            sm.br[1] = gbr[(size_t)n * 3 + 1];
            sm.br[2] = gbr[(size_t)n * 3 + 2];
        }
    }
    __syncthreads();

    uint32_t* const hSp = sm.hS[w];
    float*    const alS = sm.alphaS[w];

    for (int tile = 0; tile < 8; tile++) {
        const long ptg = (long)n * NPTS + w * 128 + tile * 16;
        const float* __restrict__ rowA = gx + (size_t)(ptg + g) * CIN;
        const float* __restrict__ rowB = rowA + 8 * CIN;

        // ---- L0 A-fragments straight from global (positions, col63 = 1.0 bias lane) ----
        uint32_t A0[8][4];
        #pragma unroll
        for (int ks = 0; ks < 8; ks++) {
            const int k0 = q + 8 * ks;
            A0[ks][0] = f2tf(rowA[k0]);
            A0[ks][1] = f2tf(rowB[k0]);
            if (ks == 7 && q == 3) { A0[ks][2] = ONE_TF; A0[ks][3] = ONE_TF; }
            else { A0[ks][2] = f2tf(rowA[k0 + 4]); A0[ks][3] = f2tf(rowB[k0 + 4]); }
        }

        // ---- L0: h1 = relu(W0 @ [pos|1]) ----
        float acc[4][4];
        #pragma unroll
        for (int nt = 0; nt < 4; nt++) acc[nt][0] = acc[nt][1] = acc[nt][2] = acc[nt][3] = 0.f;
        #pragma unroll
        for (int ks = 0; ks < 8; ks++) {
            #pragma unroll
            for (int nt = 0; nt < 4; nt++) {
                uint2 b = *reinterpret_cast<const uint2*>(&sm.W0[(nt * 8 + g) * S68 + 8 * ks + 2 * q]);
                mma_tf32(acc[nt][0], acc[nt][1], acc[nt][2], acc[nt][3],
                         A0[ks][0], A0[ks][1], A0[ks][2], A0[ks][3], b.x, b.y);
            }
        }

        // ---- direction A-fragments (cols 32..58 from x, col 59 = 1.0, 60-63 = 0) ----
        uint32_t AD[4][4];
        #pragma unroll
        for (int ks2 = 0; ks2 < 4; ks2++) {
            const int c0 = q + 8 * (ks2 + 4);           // 32..59
            if (ks2 == 3) {
                if (q == 3) { AD[3][0] = ONE_TF; AD[3][1] = ONE_TF; }
                else { AD[3][0] = f2tf(rowA[c0 + 31]); AD[3][1] = f2tf(rowB[c0 + 31]); }
                AD[3][2] = 0u; AD[3][3] = 0u;           // cols 60..63
            } else {
                AD[ks2][0] = f2tf(rowA[c0 + 31]);
                AD[ks2][1] = f2tf(rowB[c0 + 31]);
                AD[ks2][2] = f2tf(rowA[c0 + 35]);
                AD[ks2][3] = f2tf(rowB[c0 + 35]);
            }
        }

        // L0 epilogue -> hS (permuted, relu, no bias add)
        #pragma unroll
        for (int nt = 0; nt < 4; nt++) {
            hSp[g * S36 + 8 * nt + off0]       = f2tf(fmaxf(acc[nt][0], 0.f));
            hSp[g * S36 + 8 * nt + off1]       = f2tf(fmaxf(acc[nt][1], 0.f));
            hSp[(g + 8) * S36 + 8 * nt + off0] = f2tf(fmaxf(acc[nt][2], 0.f));
            hSp[(g + 8) * S36 + 8 * nt + off1] = f2tf(fmaxf(acc[nt][3], 0.f));
        }
        __syncwarp();

        // ---- L1: h2 = relu(W1 @ h1 + b1) ----
        #pragma unroll
        for (int nt = 0; nt < 4; nt++) acc[nt][0] = acc[nt][1] = acc[nt][2] = acc[nt][3] = 0.f;
        #pragma unroll
        for (int ks = 0; ks < 4; ks++) {
            uint2 aA = *reinterpret_cast<const uint2*>(&hSp[g * S36 + 8 * ks + 2 * q]);
            uint2 aB = *reinterpret_cast<const uint2*>(&hSp[(g + 8) * S36 + 8 * ks + 2 * q]);
            #pragma unroll
            for (int nt = 0; nt < 4; nt++) {
                uint2 b = *reinterpret_cast<const uint2*>(&sm.W1[(nt * 8 + g) * S36 + 8 * ks + 2 * q]);
                mma_tf32(acc[nt][0], acc[nt][1], acc[nt][2], acc[nt][3],
                         aA.x, aB.x, aA.y, aB.y, b.x, b.y);
            }
        }
        __syncwarp();
        #pragma unroll
        for (int nt = 0; nt < 4; nt++) {
            const int col = nt * 8 + 2 * q;
            float bc0 = sm.b1[col], bc1 = sm.b1[col + 1];
            hSp[g * S36 + 8 * nt + off0]       = f2tf(fmaxf(acc[nt][0] + bc0, 0.f));
            hSp[g * S36 + 8 * nt + off1]       = f2tf(fmaxf(acc[nt][1] + bc1, 0.f));
            hSp[(g + 8) * S36 + 8 * nt + off0] = f2tf(fmaxf(acc[nt][2] + bc0, 0.f));
            hSp[(g + 8) * S36 + 8 * nt + off1] = f2tf(fmaxf(acc[nt][3] + bc1, 0.f));
        }
        __syncwarp();

        // ---- L2: [feature | alpha] = Wfa @ h2 + bfa ----
        float acc5[5][4];
        #pragma unroll
        for (int nt = 0; nt < 5; nt++) acc5[nt][0] = acc5[nt][1] = acc5[nt][2] = acc5[nt][3] = 0.f;
        #pragma unroll
        for (int ks = 0; ks < 4; ks++) {
            uint2 aA = *reinterpret_cast<const uint2*>(&hSp[g * S36 + 8 * ks + 2 * q]);
            uint2 aB = *reinterpret_cast<const uint2*>(&hSp[(g + 8) * S36 + 8 * ks + 2 * q]);
            #pragma unroll
            for (int nt = 0; nt < 5; nt++) {
                uint2 b = *reinterpret_cast<const uint2*>(&sm.Wfa[(nt * 8 + g) * S36 + 8 * ks + 2 * q]);
                mma_tf32(acc5[nt][0], acc5[nt][1], acc5[nt][2], acc5[nt][3],
                         aA.x, aB.x, aA.y, aB.y, b.x, b.y);
            }
        }
        __syncwarp();
        #pragma unroll
        for (int nt = 0; nt < 4; nt++) {           // feature (no relu) -> hS
            const int col = nt * 8 + 2 * q;
            float bc0 = sm.bfa[col], bc1 = sm.bfa[col + 1];
            hSp[g * S36 + 8 * nt + off0]       = f2tf(acc5[nt][0] + bc0);
            hSp[g * S36 + 8 * nt + off1]       = f2tf(acc5[nt][1] + bc1);
            hSp[(g + 8) * S36 + 8 * nt + off0] = f2tf(acc5[nt][2] + bc0);
            hSp[(g + 8) * S36 + 8 * nt + off1] = f2tf(acc5[nt][3] + bc1);
        }
        if (q == 0) {                              // alpha = col 32
            float ba = sm.bfa[32];
            alS[g]     = acc5[4][0] + ba;
            alS[g + 8] = acc5[4][2] + ba;
        }
        __syncwarp();

        // ---- L3: hd = relu(Wd @ [feat|dirs|1]) ----
        #pragma unroll
        for (int nt = 0; nt < 4; nt++) acc[nt][0] = acc[nt][1] = acc[nt][2] = acc[nt][3] = 0.f;
        #pragma unroll
        for (int ks = 0; ks < 8; ks++) {
            uint32_t a0, a1, a2, a3;
            if (ks < 4) {
                uint2 aA = *reinterpret_cast<const uint2*>(&hSp[g * S36 + 8 * ks + 2 * q]);
                uint2 aB = *reinterpret_cast<const uint2*>(&hSp[(g + 8) * S36 + 8 * ks + 2 * q]);
                a0 = aA.x; a1 = aB.x; a2 = aA.y; a3 = aB.y;
            } else {
                a0 = AD[ks - 4][0]; a1 = AD[ks - 4][1]; a2 = AD[ks - 4][2]; a3 = AD[ks - 4][3];
            }
            #pragma unroll
            for (int nt = 0; nt < 4; nt++) {
                uint2 b = *reinterpret_cast<const uint2*>(&sm.Wd[(nt * 8 + g) * S68 + 8 * ks + 2 * q]);
                mma_tf32(acc[nt][0], acc[nt][1], acc[nt][2], acc[nt][3], a0, a1, a2, a3, b.x, b.y);
            }
        }
        __syncwarp();
        #pragma unroll
        for (int nt = 0; nt < 4; nt++) {
            hSp[g * S36 + 8 * nt + off0]       = f2tf(fmaxf(acc[nt][0], 0.f));
            hSp[g * S36 + 8 * nt + off1]       = f2tf(fmaxf(acc[nt][1], 0.f));
            hSp[(g + 8) * S36 + 8 * nt + off0] = f2tf(fmaxf(acc[nt][2], 0.f));
            hSp[(g + 8) * S36 + 8 * nt + off1] = f2tf(fmaxf(acc[nt][3], 0.f));
        }
        __syncwarp();

        // ---- L4: rgb = Wr @ hd + br ----
        float r0 = 0.f, r1 = 0.f, r2 = 0.f, r3 = 0.f;
        #pragma unroll
        for (int ks = 0; ks < 4; ks++) {
            uint2 aA = *reinterpret_cast<const uint2*>(&hSp[g * S36 + 8 * ks + 2 * q]);
            uint2 aB = *reinterpret_cast<const uint2*>(&hSp[(g + 8) * S36 + 8 * ks + 2 * q]);
            uint2 b = *reinterpret_cast<const uint2*>(&sm.Wr[g * S36 + 8 * ks + 2 * q]);
            mma_tf32(r0, r1, r2, r3, aA.x, aB.x, aA.y, aB.y, b.x, b.y);
        }

        // ---- write [rgb, alpha] ----
        float2* out2 = reinterpret_cast<float2*>(gout);
        if (q == 0) {
            out2[(ptg + g) * 2]     = make_float2(r0 + sm.br[0], r1 + sm.br[1]);
            out2[(ptg + g + 8) * 2] = make_float2(r2 + sm.br[0], r3 + sm.br[1]);
        } else if (q == 1) {
            out2[(ptg + g) * 2 + 1]     = make_float2(r0 + sm.br[2], alS[g]);
            out2[(ptg + g + 8) * 2 + 1] = make_float2(r2 + sm.br[2], alS[g + 8]);
        }
        __syncwarp();
    }
}

extern "C" void kernel_launch(void* const* d_in, const int* in_sizes, int n_in,
                              void* d_out, int out_size)
{
    const float* gx  = (const float*)d_in[0];
    const float* gW0 = (const float*)d_in[1];
    const float* gb0 = (const float*)d_in[2];
    const float* gW1 = (const float*)d_in[3];
    const float* gb1 = (const float*)d_in[4];
    const float* gWa = (const float*)d_in[5];
    const float* gba = (const float*)d_in[6];
    const float* gWf = (const float*)d_in[7];
    const float* gbf = (const float*)d_in[8];
    const float* gWd = (const float*)d_in[9];
    const float* gbd = (const float*)d_in[10];
    const float* gWr = (const float*)d_in[11];
    const float* gbr = (const float*)d_in[12];
    float* gout = (float*)d_out;

    const int smem_bytes = (int)sizeof(Smem);
    cudaFuncSetAttribute(kilonerf_mma_kernel,
                         cudaFuncAttributeMaxDynamicSharedMemorySize, smem_bytes);

    kilonerf_mma_kernel<<<N_NET, TPB, smem_bytes>>>(
        gx, gW0, gb0, gW1, gb1, gWa, gba, gWf, gbf, gWd, gbd, gWr, gbr, gout);
}

// round 4
// speedup vs baseline: 3.0225x; 1.0023x over previous
#include <cuda_runtime.h>
#include <cstdint>

#define N_NET 4096
#define NPTS  512
#define PC    63
#define DC    27
#define CIN   90
#define TPB   128

#define S68 68   // stride for K=64 weight tiles (mod 32 == 4)
#define S36 36   // stride for K=32 tiles / activations (mod 32 == 4)

struct __align__(16) Smem {
    uint32_t W0[32 * S68];    // natural k order, word63 = b0 (bias-in-K)
    uint32_t W1[32 * S36];    // natural
    uint32_t Wfa[40 * S36];   // rows 0-31 Wf, row 32 Wa, 33-39 zero
    uint32_t Wd[32 * S68];    // words0-31=Wf-in cols, 32-57=gWd cols33-58, 58=gWd col32, 59=bd, 60-63=0
    uint32_t Wr[8 * S36];     // rows 0-2 Wr, 3-7 zero
    float b1[32];
    float bfa[34];            // [32] = ba
    float br[4];
    uint32_t hS[4][16 * S36]; // per-warp activation scratch (natural col order)
    float alphaS[4][16];
};

#define ZWORDS (32*S68 + 32*S36 + 40*S36 + 32*S68 + 8*S36 + 32 + 34 + 4)

__device__ __forceinline__ uint32_t f2tf(float x) {
    uint32_t u;
    asm("cvt.rna.tf32.f32 %0, %1;" : "=r"(u) : "f"(x));
    return u;
}

__device__ __forceinline__ void mma_tf32(float& c0, float& c1, float& c2, float& c3,
                                         uint32_t a0, uint32_t a1, uint32_t a2, uint32_t a3,
                                         uint32_t b0, uint32_t b1) {
    asm("mma.sync.aligned.m16n8k8.row.col.f32.tf32.tf32.f32 "
        "{%0,%1,%2,%3}, {%4,%5,%6,%7}, {%8,%9}, {%0,%1,%2,%3};"
        : "+f"(c0), "+f"(c1), "+f"(c2), "+f"(c3)
        : "r"(a0), "r"(a1), "r"(a2), "r"(a3), "r"(b0), "r"(b1));
}

#define ONE_TF 0x3F800000u

__global__ __launch_bounds__(TPB, 5) void kilonerf_mma_kernel(
    const float* __restrict__ gx,
    const float* __restrict__ gW0, const float* __restrict__ gb0,
    const float* __restrict__ gW1, const float* __restrict__ gb1,
    const float* __restrict__ gWa, const float* __restrict__ gba,
    const float* __restrict__ gWf, const float* __restrict__ gbf,
    const float* __restrict__ gWd, const float* __restrict__ gbd,
    const float* __restrict__ gWr, const float* __restrict__ gbr,
    float* __restrict__ gout)
{
    extern __shared__ char smem_raw[];
    Smem& sm = *reinterpret_cast<Smem*>(smem_raw);

    const int n = blockIdx.x;
    const int t = threadIdx.x;
    const int w = t >> 5;
    const int l = t & 31;
    const int g = l >> 2;        // groupID (row within 8)
    const int q = l & 3;         // threadID_in_group
    const int q2 = 2 * q;        // output col base within an 8-group

    // ---------------- zero weights+biases, then stage (natural k order, tf32) ----------------
    {
        uint32_t* zp = sm.W0;
        for (int i = t; i < ZWORDS; i += TPB) zp[i] = 0u;
        __syncthreads();

        const float* p;
        p = gW0 + (size_t)n * 32 * 63;
        for (int i = t; i < 32 * 63; i += TPB) { int r = i / 63, k = i - r * 63; sm.W0[r * S68 + k] = f2tf(p[i]); }
        p = gW1 + (size_t)n * 1024;
        for (int i = t; i < 1024; i += TPB) { int r = i >> 5, k = i & 31; sm.W1[r * S36 + k] = f2tf(p[i]); }
        p = gWf + (size_t)n * 1024;
        for (int i = t; i < 1024; i += TPB) { int r = i >> 5, k = i & 31; sm.Wfa[r * S36 + k] = f2tf(p[i]); }
        p = gWd + (size_t)n * 32 * 59;
        for (int i = t; i < 32 * 59; i += TPB) {
            int r = i / 59, c = i - r * 59;
            int wd = (c < 32) ? c : ((c == 32) ? 58 : (c - 1));  // dir0 -> word58, dirs1..26 -> 32..57
            sm.Wd[r * S68 + wd] = f2tf(p[i]);
        }
        if (t < 32) {
            sm.Wfa[32 * S36 + t] = f2tf(gWa[(size_t)n * 32 + t]);   // Wa row (natural)
            sm.W0[t * S68 + 63] = f2tf(gb0[(size_t)n * 32 + t]);    // b0 at word 63
            sm.Wd[t * S68 + 59] = f2tf(gbd[(size_t)n * 32 + t]);    // bd at word 59
            sm.b1[t]  = gb1[(size_t)n * 32 + t];
            sm.bfa[t] = gbf[(size_t)n * 32 + t];
        }
        if (t >= 32 && t < 128) { int i = t - 32; int r = i >> 5, k = i & 31; sm.Wr[r * S36 + k] = f2tf(gWr[(size_t)n * 96 + i]); }
        if (t == 0) {
            sm.bfa[32] = gba[n];
            sm.br[0] = gbr[(size_t)n * 3 + 0];
            sm.br[1] = gbr[(size_t)n * 3 + 1];
            sm.br[2] = gbr[(size_t)n * 3 + 2];
        }
    }
    __syncthreads();

    uint32_t* const hSp = sm.hS[w];
    float*    const alS = sm.alphaS[w];

    for (int tile = 0; tile < 8; tile++) {
        const long ptg = (long)n * NPTS + w * 128 + tile * 16;
        const float* __restrict__ rowA = gx + (size_t)(ptg + g) * CIN;
        const float* __restrict__ rowB = rowA + 8 * CIN;

        // ---- L0 A-fragments: aligned float2 from global; pair slot pi=4ks+q -> cols (2pi, 2pi+1) ----
        uint32_t A0[8][4];
        #pragma unroll
        for (int ks = 0; ks < 8; ks++) {
            const int c0 = 8 * ks + q2;          // 2*pi
            if (ks == 7 && q == 3) {             // pair (col62, bias-one)
                A0[7][0] = f2tf(rowA[62]); A0[7][1] = f2tf(rowB[62]);
                A0[7][2] = ONE_TF;         A0[7][3] = ONE_TF;
            } else {
                float2 vA = *reinterpret_cast<const float2*>(rowA + c0);
                float2 vB = *reinterpret_cast<const float2*>(rowB + c0);
                A0[ks][0] = f2tf(vA.x); A0[ks][2] = f2tf(vA.y);
                A0[ks][1] = f2tf(vB.x); A0[ks][3] = f2tf(vB.y);
            }
        }

        // ---- L0: h1 = relu(W0 @ [pos|1]) ----
        float acc[4][4];
        #pragma unroll
        for (int nt = 0; nt < 4; nt++) acc[nt][0] = acc[nt][1] = acc[nt][2] = acc[nt][3] = 0.f;
        #pragma unroll
        for (int ks = 0; ks < 8; ks++) {
            #pragma unroll
            for (int nt = 0; nt < 4; nt++) {
                uint2 b = *reinterpret_cast<const uint2*>(&sm.W0[(nt * 8 + g) * S68 + 8 * ks + q2]);
                mma_tf32(acc[nt][0], acc[nt][1], acc[nt][2], acc[nt][3],
                         A0[ks][0], A0[ks][1], A0[ks][2], A0[ks][3], b.x, b.y);
            }
        }

        // ---- direction A-fragments: pi2=4*ks2+q; pi2<=12 -> dirs (cols 64+2pi2, 65+2pi2);
        //      pi2==13 -> (col63=dir0, 1.0); pi2>=14 -> zeros ----
        uint32_t AD[4][4];
        #pragma unroll
        for (int ks2 = 0; ks2 < 4; ks2++) {
            const int pi2 = 4 * ks2 + q;
            if (pi2 <= 12) {
                float2 vA = *reinterpret_cast<const float2*>(rowA + 64 + 2 * pi2);
                float2 vB = *reinterpret_cast<const float2*>(rowB + 64 + 2 * pi2);
                AD[ks2][0] = f2tf(vA.x); AD[ks2][2] = f2tf(vA.y);
                AD[ks2][1] = f2tf(vB.x); AD[ks2][3] = f2tf(vB.y);
            } else if (pi2 == 13) {
                AD[ks2][0] = f2tf(rowA[63]); AD[ks2][1] = f2tf(rowB[63]);
                AD[ks2][2] = ONE_TF;         AD[ks2][3] = ONE_TF;
            } else {
                AD[ks2][0] = AD[ks2][1] = AD[ks2][2] = AD[ks2][3] = 0u;
            }
        }

        // L0 epilogue -> hS natural cols (STS.64), relu, bias already folded
        #pragma unroll
        for (int nt = 0; nt < 4; nt++) {
            uint2 u01 = make_uint2(f2tf(fmaxf(acc[nt][0], 0.f)), f2tf(fmaxf(acc[nt][1], 0.f)));
            uint2 u23 = make_uint2(f2tf(fmaxf(acc[nt][2], 0.f)), f2tf(fmaxf(acc[nt][3], 0.f)));
            *reinterpret_cast<uint2*>(&hSp[g * S36 + nt * 8 + q2])       = u01;
            *reinterpret_cast<uint2*>(&hSp[(g + 8) * S36 + nt * 8 + q2]) = u23;
        }
        __syncwarp();

        // ---- L1: h2 = relu(W1 @ h1 + b1) ----
        #pragma unroll
        for (int nt = 0; nt < 4; nt++) acc[nt][0] = acc[nt][1] = acc[nt][2] = acc[nt][3] = 0.f;
        #pragma unroll
        for (int ks = 0; ks < 4; ks++) {
            uint2 aA = *reinterpret_cast<const uint2*>(&hSp[g * S36 + 8 * ks + q2]);
            uint2 aB = *reinterpret_cast<const uint2*>(&hSp[(g + 8) * S36 + 8 * ks + q2]);
            #pragma unroll
            for (int nt = 0; nt < 4; nt++) {
                uint2 b = *reinterpret_cast<const uint2*>(&sm.W1[(nt * 8 + g) * S36 + 8 * ks + q2]);
                mma_tf32(acc[nt][0], acc[nt][1], acc[nt][2], acc[nt][3],
                         aA.x, aB.x, aA.y, aB.y, b.x, b.y);
            }
        }
        __syncwarp();
        #pragma unroll
        for (int nt = 0; nt < 4; nt++) {
            const int col = nt * 8 + q2;
            float bc0 = sm.b1[col], bc1 = sm.b1[col + 1];
            uint2 u01 = make_uint2(f2tf(fmaxf(acc[nt][0] + bc0, 0.f)), f2tf(fmaxf(acc[nt][1] + bc1, 0.f)));
            uint2 u23 = make_uint2(f2tf(fmaxf(acc[nt][2] + bc0, 0.f)), f2tf(fmaxf(acc[nt][3] + bc1, 0.f)));
            *reinterpret_cast<uint2*>(&hSp[g * S36 + col])       = u01;
            *reinterpret_cast<uint2*>(&hSp[(g + 8) * S36 + col]) = u23;
        }
        __syncwarp();

        // ---- L2: [feature | alpha] = Wfa @ h2 + bfa ----
        float acc5[5][4];
        #pragma unroll
        for (int nt = 0; nt < 5; nt++) acc5[nt][0] = acc5[nt][1] = acc5[nt][2] = acc5[nt][3] = 0.f;
        #pragma unroll
        for (int ks = 0; ks < 4; ks++) {
            uint2 aA = *reinterpret_cast<const uint2*>(&hSp[g * S36 + 8 * ks + q2]);
            uint2 aB = *reinterpret_cast<const uint2*>(&hSp[(g + 8) * S36 + 8 * ks + q2]);
            #pragma unroll
            for (int nt = 0; nt < 5; nt++) {
                uint2 b = *reinterpret_cast<const uint2*>(&sm.Wfa[(nt * 8 + g) * S36 + 8 * ks + q2]);
                mma_tf32(acc5[nt][0], acc5[nt][1], acc5[nt][2], acc5[nt][3],
                         aA.x, aB.x, aA.y, aB.y, b.x, b.y);
            }
        }
        __syncwarp();
        #pragma unroll
        for (int nt = 0; nt < 4; nt++) {           // feature (no relu) -> hS
            const int col = nt * 8 + q2;
            float bc0 = sm.bfa[col], bc1 = sm.bfa[col + 1];
            uint2 u01 = make_uint2(f2tf(acc5[nt][0] + bc0), f2tf(acc5[nt][1] + bc1));
            uint2 u23 = make_uint2(f2tf(acc5[nt][2] + bc0), f2tf(acc5[nt][3] + bc1));
            *reinterpret_cast<uint2*>(&hSp[g * S36 + col])       = u01;
            *reinterpret_cast<uint2*>(&hSp[(g + 8) * S36 + col]) = u23;
        }
        if (q == 0) {                              // alpha = col 32
            float ba = sm.bfa[32];
            alS[g]     = acc5[4][0] + ba;
            alS[g + 8] = acc5[4][2] + ba;
        }
        __syncwarp();

        // ---- L3: hd = relu(Wd @ [feat|dirs|1]) ----
        #pragma unroll
        for (int nt = 0; nt < 4; nt++) acc[nt][0] = acc[nt][1] = acc[nt][2] = acc[nt][3] = 0.f;
        #pragma unroll
        for (int ks = 0; ks < 8; ks++) {
            uint32_t a0, a1, a2, a3;
            if (ks < 4) {
                uint2 aA = *reinterpret_cast<const uint2*>(&hSp[g * S36 + 8 * ks + q2]);
                uint2 aB = *reinterpret_cast<const uint2*>(&hSp[(g + 8) * S36 + 8 * ks + q2]);
                a0 = aA.x; a1 = aB.x; a2 = aA.y; a3 = aB.y;
            } else {
                a0 = AD[ks - 4][0]; a1 = AD[ks - 4][1]; a2 = AD[ks - 4][2]; a3 = AD[ks - 4][3];
            }
            #pragma unroll
            for (int nt = 0; nt < 4; nt++) {
                uint2 b = *reinterpret_cast<const uint2*>(&sm.Wd[(nt * 8 + g) * S68 + 8 * ks + q2]);
                mma_tf32(acc[nt][0], acc[nt][1], acc[nt][2], acc[nt][3], a0, a1, a2, a3, b.x, b.y);
            }
        }
        __syncwarp();
        #pragma unroll
        for (int nt = 0; nt < 4; nt++) {
            uint2 u01 = make_uint2(f2tf(fmaxf(acc[nt][0], 0.f)), f2tf(fmaxf(acc[nt][1], 0.f)));
            uint2 u23 = make_uint2(f2tf(fmaxf(acc[nt][2], 0.f)), f2tf(fmaxf(acc[nt][3], 0.f)));
            *reinterpret_cast<uint2*>(&hSp[g * S36 + nt * 8 + q2])       = u01;
            *reinterpret_cast<uint2*>(&hSp[(g + 8) * S36 + nt * 8 + q2]) = u23;
        }
        __syncwarp();

        // ---- L4: rgb = Wr @ hd + br ----
        float r0 = 0.f, r1 = 0.f, r2 = 0.f, r3 = 0.f;
        #pragma unroll
        for (int ks = 0; ks < 4; ks++) {
            uint2 aA = *reinterpret_cast<const uint2*>(&hSp[g * S36 + 8 * ks + q2]);
            uint2 aB = *reinterpret_cast<const uint2*>(&hSp[(g + 8) * S36 + 8 * ks + q2]);
            uint2 b = *reinterpret_cast<const uint2*>(&sm.Wr[g * S36 + 8 * ks + q2]);
            mma_tf32(r0, r1, r2, r3, aA.x, aB.x, aA.y, aB.y, b.x, b.y);
        }

        // ---- write [rgb, alpha] ----
        float2* out2 = reinterpret_cast<float2*>(gout);
        if (q == 0) {
            out2[(ptg + g) * 2]     = make_float2(r0 + sm.br[0], r1 + sm.br[1]);
            out2[(ptg + g + 8) * 2] = make_float2(r2 + sm.br[0], r3 + sm.br[1]);
        } else if (q == 1) {
            out2[(ptg + g) * 2 + 1]     = make_float2(r0 + sm.br[2], alS[g]);
            out2[(ptg + g + 8) * 2 + 1] = make_float2(r2 + sm.br[2], alS[g + 8]);
        }
        __syncwarp();
    }
}

extern "C" void kernel_launch(void* const* d_in, const int* in_sizes, int n_in,
                              void* d_out, int out_size)
{
    const float* gx  = (const float*)d_in[0];
    const float* gW0 = (const float*)d_in[1];
    const float* gb0 = (const float*)d_in[2];
    const float* gW1 = (const float*)d_in[3];
    const float* gb1 = (const float*)d_in[4];
    const float* gWa = (const float*)d_in[5];
    const float* gba = (const float*)d_in[6];
    const float* gWf = (const float*)d_in[7];
    const float* gbf = (const float*)d_in[8];
    const float* gWd = (const float*)d_in[9];
    const float* gbd = (const float*)d_in[10];
    const float* gWr = (const float*)d_in[11];
    const float* gbr = (const float*)d_in[12];
    float* gout = (float*)d_out;

    const int smem_bytes = (int)sizeof(Smem);
    cudaFuncSetAttribute(kilonerf_mma_kernel,
                         cudaFuncAttributeMaxDynamicSharedMemorySize, smem_bytes);

    kilonerf_mma_kernel<<<N_NET, TPB, smem_bytes>>>(
        gx, gW0, gb0, gW1, gb1, gWa, gba, gWf, gbf, gWd, gbd, gWr, gbr, gout);
}

// round 5
// speedup vs baseline: 3.2731x; 1.0829x over previous
#include <cuda_runtime.h>
#include <cstdint>

#define N_NET 4096
#define NPTS  512
#define PC    63
#define DC    27
#define CIN   90
#define TPB   128

#define S68 68   // stride for K=64 weight tiles (mod 32 == 4)
#define S36 36   // stride for K=32 tiles (mod 32 == 4)

struct __align__(16) Smem {
    uint32_t W0[32 * S68];    // natural k order, word63 = b0 (bias-in-K)
    uint32_t W1[32 * S36];    // natural
    uint32_t Wfa[40 * S36];   // rows 0-31 Wf, row 32 Wa, 33-39 zero
    uint32_t Wd[32 * S68];    // words0-31=feat cols, 32-57=gWd cols33-58, 58=gWd col32, 59=bd, 60-63=0
    uint32_t Wr[8 * S36];     // rows 0-2 Wr, 3-7 zero
    float b1[32];
    float bfa[34];            // [32] = ba
    float br[4];
};

#define ZWORDS (32*S68 + 32*S36 + 40*S36 + 32*S68 + 8*S36 + 32 + 34 + 4)

__device__ __forceinline__ uint32_t f2tf(float x) {
    uint32_t u;
    asm("cvt.rna.tf32.f32 %0, %1;" : "=r"(u) : "f"(x));
    return u;
}

// a0=A[g][lab0], a1=A[g+8][lab0], a2=A[g][lab1], a3=A[g+8][lab1]
// c0=D[g][2q], c1=D[g][2q+1], c2=D[g+8][2q], c3=D[g+8][2q+1]
__device__ __forceinline__ void mma_tf32(float& c0, float& c1, float& c2, float& c3,
                                         uint32_t a0, uint32_t a1, uint32_t a2, uint32_t a3,
                                         uint32_t b0, uint32_t b1) {
    asm("mma.sync.aligned.m16n8k8.row.col.f32.tf32.tf32.f32 "
        "{%0,%1,%2,%3}, {%4,%5,%6,%7}, {%8,%9}, {%0,%1,%2,%3};"
        : "+f"(c0), "+f"(c1), "+f"(c2), "+f"(c3)
        : "r"(a0), "r"(a1), "r"(a2), "r"(a3), "r"(b0), "r"(b1));
}

#define ONE_TF 0x3F800000u

__global__ __launch_bounds__(TPB, 5) void kilonerf_mma_kernel(
    const float* __restrict__ gx,
    const float* __restrict__ gW0, const float* __restrict__ gb0,
    const float* __restrict__ gW1, const float* __restrict__ gb1,
    const float* __restrict__ gWa, const float* __restrict__ gba,
    const float* __restrict__ gWf, const float* __restrict__ gbf,
    const float* __restrict__ gWd, const float* __restrict__ gbd,
    const float* __restrict__ gWr, const float* __restrict__ gbr,
    float* __restrict__ gout)
{
    extern __shared__ char smem_raw[];
    Smem& sm = *reinterpret_cast<Smem*>(smem_raw);

    const int n = blockIdx.x;
    const int t = threadIdx.x;
    const int w = t >> 5;
    const int l = t & 31;
    const int g = l >> 2;        // groupID
    const int q = l & 3;         // threadID_in_group
    const int q2 = 2 * q;

    // ---------------- zero weights+biases, then stage (natural k order, tf32) ----------------
    {
        uint32_t* zp = sm.W0;
        for (int i = t; i < ZWORDS; i += TPB) zp[i] = 0u;
        __syncthreads();

        const float* p;
        p = gW0 + (size_t)n * 32 * 63;
        for (int i = t; i < 32 * 63; i += TPB) { int r = i / 63, k = i - r * 63; sm.W0[r * S68 + k] = f2tf(p[i]); }
        p = gW1 + (size_t)n * 1024;
        for (int i = t; i < 1024; i += TPB) { int r = i >> 5, k = i & 31; sm.W1[r * S36 + k] = f2tf(p[i]); }
        p = gWf + (size_t)n * 1024;
        for (int i = t; i < 1024; i += TPB) { int r = i >> 5, k = i & 31; sm.Wfa[r * S36 + k] = f2tf(p[i]); }
        p = gWd + (size_t)n * 32 * 59;
        for (int i = t; i < 32 * 59; i += TPB) {
            int r = i / 59, c = i - r * 59;
            int wd = (c < 32) ? c : ((c == 32) ? 58 : (c - 1));  // dir0 -> word58, dirs1..26 -> 32..57
            sm.Wd[r * S68 + wd] = f2tf(p[i]);
        }
        if (t < 32) {
            sm.Wfa[32 * S36 + t] = f2tf(gWa[(size_t)n * 32 + t]);   // Wa row
            sm.W0[t * S68 + 63] = f2tf(gb0[(size_t)n * 32 + t]);    // b0 at word 63
            sm.Wd[t * S68 + 59] = f2tf(gbd[(size_t)n * 32 + t]);    // bd at word 59
            sm.b1[t]  = gb1[(size_t)n * 32 + t];
            sm.bfa[t] = gbf[(size_t)n * 32 + t];
        }
        if (t >= 32 && t < 128) { int i = t - 32; int r = i >> 5, k = i & 31; sm.Wr[r * S36 + k] = f2tf(gWr[(size_t)n * 96 + i]); }
        if (t == 0) {
            sm.bfa[32] = gba[n];
            sm.br[0] = gbr[(size_t)n * 3 + 0];
            sm.br[1] = gbr[(size_t)n * 3 + 1];
            sm.br[2] = gbr[(size_t)n * 3 + 2];
        }
    }
    __syncthreads();

    for (int tile = 0; tile < 8; tile++) {
        const long ptg = (long)n * NPTS + w * 128 + tile * 16;
        const float* __restrict__ rowA = gx + (size_t)(ptg + g) * CIN;
        const float* __restrict__ rowB = rowA + 8 * CIN;

        // ---- L0 A-fragments: aligned float2 from global; slot pi=4ks+q -> cols (2pi, 2pi+1) ----
        uint32_t A0[8][4];
        #pragma unroll
        for (int ks = 0; ks < 8; ks++) {
            const int c0 = 8 * ks + q2;
            if (ks == 7 && q == 3) {             // pair (col62, bias-one)
                A0[7][0] = f2tf(rowA[62]); A0[7][1] = f2tf(rowB[62]);
                A0[7][2] = ONE_TF;         A0[7][3] = ONE_TF;
            } else {
                float2 vA = *reinterpret_cast<const float2*>(rowA + c0);
                float2 vB = *reinterpret_cast<const float2*>(rowB + c0);
                A0[ks][0] = f2tf(vA.x); A0[ks][2] = f2tf(vA.y);
                A0[ks][1] = f2tf(vB.x); A0[ks][3] = f2tf(vB.y);
            }
        }

        // ---- direction A-fragments: pi2=4*ks2+q ----
        uint32_t AD[4][4];
        #pragma unroll
        for (int ks2 = 0; ks2 < 4; ks2++) {
            const int pi2 = 4 * ks2 + q;
            if (pi2 <= 12) {
                float2 vA = *reinterpret_cast<const float2*>(rowA + 64 + 2 * pi2);
                float2 vB = *reinterpret_cast<const float2*>(rowB + 64 + 2 * pi2);
                AD[ks2][0] = f2tf(vA.x); AD[ks2][2] = f2tf(vA.y);
                AD[ks2][1] = f2tf(vB.x); AD[ks2][3] = f2tf(vB.y);
            } else if (pi2 == 13) {
                AD[ks2][0] = f2tf(rowA[63]); AD[ks2][1] = f2tf(rowB[63]);
                AD[ks2][2] = ONE_TF;         AD[ks2][3] = ONE_TF;
            } else {
                AD[ks2][0] = AD[ks2][1] = AD[ks2][2] = AD[ks2][3] = 0u;
            }
        }

        // ---- L0: h1 = relu(W0 @ [pos|1]) ----
        float acc[4][4];
        #pragma unroll
        for (int nt = 0; nt < 4; nt++) acc[nt][0] = acc[nt][1] = acc[nt][2] = acc[nt][3] = 0.f;
        #pragma unroll
        for (int ks = 0; ks < 8; ks++) {
            #pragma unroll
            for (int nt = 0; nt < 4; nt++) {
                uint2 b = *reinterpret_cast<const uint2*>(&sm.W0[(nt * 8 + g) * S68 + 8 * ks + q2]);
                mma_tf32(acc[nt][0], acc[nt][1], acc[nt][2], acc[nt][3],
                         A0[ks][0], A0[ks][1], A0[ks][2], A0[ks][3], b.x, b.y);
            }
        }
        // C-fragment == next layer's A-fragment: repack in mma-arg order (a0,a1,a2,a3)
        uint32_t h1[4][4];
        #pragma unroll
        for (int nt = 0; nt < 4; nt++) {
            h1[nt][0] = f2tf(fmaxf(acc[nt][0], 0.f));   // (g,   lab0)
            h1[nt][2] = f2tf(fmaxf(acc[nt][1], 0.f));   // (g,   lab1)
            h1[nt][1] = f2tf(fmaxf(acc[nt][2], 0.f));   // (g+8, lab0)
            h1[nt][3] = f2tf(fmaxf(acc[nt][3], 0.f));   // (g+8, lab1)
        }

        // ---- L1: h2 = relu(W1 @ h1 + b1) ----
        #pragma unroll
        for (int nt = 0; nt < 4; nt++) acc[nt][0] = acc[nt][1] = acc[nt][2] = acc[nt][3] = 0.f;
        #pragma unroll
        for (int ks = 0; ks < 4; ks++) {
            #pragma unroll
            for (int nt = 0; nt < 4; nt++) {
                uint2 b = *reinterpret_cast<const uint2*>(&sm.W1[(nt * 8 + g) * S36 + 8 * ks + q2]);
                mma_tf32(acc[nt][0], acc[nt][1], acc[nt][2], acc[nt][3],
                         h1[ks][0], h1[ks][1], h1[ks][2], h1[ks][3], b.x, b.y);
            }
        }
        uint32_t h2[4][4];
        #pragma unroll
        for (int nt = 0; nt < 4; nt++) {
            const int col = nt * 8 + q2;
            float bc0 = sm.b1[col], bc1 = sm.b1[col + 1];
            h2[nt][0] = f2tf(fmaxf(acc[nt][0] + bc0, 0.f));
            h2[nt][2] = f2tf(fmaxf(acc[nt][1] + bc1, 0.f));
            h2[nt][1] = f2tf(fmaxf(acc[nt][2] + bc0, 0.f));
            h2[nt][3] = f2tf(fmaxf(acc[nt][3] + bc1, 0.f));
        }

        // ---- L2: [feature | alpha] = Wfa @ h2 + bfa ----
        float acc5[5][4];
        #pragma unroll
        for (int nt = 0; nt < 5; nt++) acc5[nt][0] = acc5[nt][1] = acc5[nt][2] = acc5[nt][3] = 0.f;
        #pragma unroll
        for (int ks = 0; ks < 4; ks++) {
            #pragma unroll
            for (int nt = 0; nt < 5; nt++) {
                uint2 b = *reinterpret_cast<const uint2*>(&sm.Wfa[(nt * 8 + g) * S36 + 8 * ks + q2]);
                mma_tf32(acc5[nt][0], acc5[nt][1], acc5[nt][2], acc5[nt][3],
                         h2[ks][0], h2[ks][1], h2[ks][2], h2[ks][3], b.x, b.y);
            }
        }
        uint32_t ft[4][4];
        #pragma unroll
        for (int nt = 0; nt < 4; nt++) {            // feature (no relu)
            const int col = nt * 8 + q2;
            float bc0 = sm.bfa[col], bc1 = sm.bfa[col + 1];
            ft[nt][0] = f2tf(acc5[nt][0] + bc0);
            ft[nt][2] = f2tf(acc5[nt][1] + bc1);
            ft[nt][1] = f2tf(acc5[nt][2] + bc0);
            ft[nt][3] = f2tf(acc5[nt][3] + bc1);
        }
        // alpha = col 32 -> held by q==0 lanes; broadcast to the group
        const float ba = sm.bfa[32];
        const float alA = __shfl_sync(0xffffffffu, acc5[4][0] + ba, l & ~3);
        const float alB = __shfl_sync(0xffffffffu, acc5[4][2] + ba, l & ~3);

        // ---- L3: hd = relu(Wd @ [feat|dirs|1]) ----
        #pragma unroll
        for (int nt = 0; nt < 4; nt++) acc[nt][0] = acc[nt][1] = acc[nt][2] = acc[nt][3] = 0.f;
        #pragma unroll
        for (int ks = 0; ks < 8; ks++) {
            uint32_t a0, a1, a2, a3;
            if (ks < 4) { a0 = ft[ks][0]; a1 = ft[ks][1]; a2 = ft[ks][2]; a3 = ft[ks][3]; }
            else        { a0 = AD[ks - 4][0]; a1 = AD[ks - 4][1]; a2 = AD[ks - 4][2]; a3 = AD[ks - 4][3]; }
            #pragma unroll
            for (int nt = 0; nt < 4; nt++) {
                uint2 b = *reinterpret_cast<const uint2*>(&sm.Wd[(nt * 8 + g) * S68 + 8 * ks + q2]);
                mma_tf32(acc[nt][0], acc[nt][1], acc[nt][2], acc[nt][3], a0, a1, a2, a3, b.x, b.y);
            }
        }
        uint32_t hd[4][4];
        #pragma unroll
        for (int nt = 0; nt < 4; nt++) {
            hd[nt][0] = f2tf(fmaxf(acc[nt][0], 0.f));
            hd[nt][2] = f2tf(fmaxf(acc[nt][1], 0.f));
            hd[nt][1] = f2tf(fmaxf(acc[nt][2], 0.f));
            hd[nt][3] = f2tf(fmaxf(acc[nt][3], 0.f));
        }

        // ---- L4: rgb = Wr @ hd + br ----
        float r0 = 0.f, r1 = 0.f, r2 = 0.f, r3 = 0.f;
        #pragma unroll
        for (int ks = 0; ks < 4; ks++) {
            uint2 b = *reinterpret_cast<const uint2*>(&sm.Wr[g * S36 + 8 * ks + q2]);
            mma_tf32(r0, r1, r2, r3, hd[ks][0], hd[ks][1], hd[ks][2], hd[ks][3], b.x, b.y);
        }

        // ---- write [rgb, alpha] ----
        float2* out2 = reinterpret_cast<float2*>(gout);
        if (q == 0) {          // cols 0,1
            out2[(ptg + g) * 2]     = make_float2(r0 + sm.br[0], r1 + sm.br[1]);
            out2[(ptg + g + 8) * 2] = make_float2(r2 + sm.br[0], r3 + sm.br[1]);
        } else if (q == 1) {   // col 2 + alpha
            out2[(ptg + g) * 2 + 1]     = make_float2(r0 + sm.br[2], alA);
            out2[(ptg + g + 8) * 2 + 1] = make_float2(r2 + sm.br[2], alB);
        }
    }
}

extern "C" void kernel_launch(void* const* d_in, const int* in_sizes, int n_in,
                              void* d_out, int out_size)
{
    const float* gx  = (const float*)d_in[0];
    const float* gW0 = (const float*)d_in[1];
    const float* gb0 = (const float*)d_in[2];
    const float* gW1 = (const float*)d_in[3];
    const float* gb1 = (const float*)d_in[4];
    const float* gWa = (const float*)d_in[5];
    const float* gba = (const float*)d_in[6];
    const float* gWf = (const float*)d_in[7];
    const float* gbf = (const float*)d_in[8];
    const float* gWd = (const float*)d_in[9];
    const float* gbd = (const float*)d_in[10];
    const float* gWr = (const float*)d_in[11];
    const float* gbr = (const float*)d_in[12];
    float* gout = (float*)d_out;

    const int smem_bytes = (int)sizeof(Smem);
    cudaFuncSetAttribute(kilonerf_mma_kernel,
                         cudaFuncAttributeMaxDynamicSharedMemorySize, smem_bytes);

    kilonerf_mma_kernel<<<N_NET, TPB, smem_bytes>>>(
        gx, gW0, gb0, gW1, gb1, gWa, gba, gWf, gbf, gWd, gbd, gWr, gbr, gout);
}